// round 14
// baseline (speedup 1.0000x reference)
#include <cuda_runtime.h>
#include <cuda_fp16.h>
#include <cuda_fp8.h>

#define NN 50000
#define EE 800000
#define FULL 0xffffffffu
#define DBINS 64

// ---------------- device scratch ----------------
__device__ __align__(16) unsigned char g_bufT[NN * 128]; // messages, fp8 e4m3 (bytes)
__device__ __align__(16) float g_bufX[NN * 128];         // layer activations (fp32)
__device__ float  g_dinv[NN];
__device__ int    g_cnt[NN];
__device__ int    g_off[NN];
__device__ int    g_cur[NN];
__device__ int    g_tot;
__device__ int    g_es[EE];          // CSR: src ids grouped by dst
__device__ int    g_order[NN];       // nodes sorted by degree (counting sort)
__device__ int    g_dbin[DBINS];
__device__ int    g_dcur[DBINS];
__device__ float2 g_Sv[NN];          // per-node per-head <g, a_src>
__device__ float2 g_Dv[NN];          // per-node per-head <g, a_dst>
__device__ float2 g_eb[EE];          // cached per-edge raw scores (2 heads)

// ---------------- helpers ----------------
__device__ __forceinline__ float lrelu(float x) { return x > 0.f ? x : 0.2f * x; }

// packed f32x2 FMA: d = a*b + d (bit-exact 2x FFMA, Blackwell FFMA2)
__device__ __forceinline__ void ffma2(unsigned long long& d, unsigned long long a,
                                      unsigned long long b) {
    asm("fma.rn.f32x2 %0, %1, %2, %0;" : "+l"(d) : "l"(a), "l"(b));
}
__device__ __forceinline__ unsigned long long pack_dup(float x) {
    unsigned long long r;
    asm("mov.b64 %0, {%1, %1};" : "=l"(r) : "r"(__float_as_uint(x)));
    return r;
}
__device__ __forceinline__ void unpack2(unsigned long long v, float& lo, float& hi) {
    unsigned a, b;
    asm("mov.b64 {%0, %1}, %2;" : "=r"(a), "=r"(b) : "l"(v));
    lo = __uint_as_float(a);
    hi = __uint_as_float(b);
}

// fp8 gather with half2 HFMA2 accumulation: 1 LDG + 8 cvt + 8 HFMA2 per 16 channels
__device__ __forceinline__ void acc16h(const uint4* __restrict__ base, size_t idx,
                                       __half2 w, __half2* acc) {
    uint4 q = __ldg(base + idx);
    unsigned v[4] = {q.x, q.y, q.z, q.w};
#pragma unroll
    for (int k = 0; k < 4; k++) {
        __half2_raw h0 = __nv_cvt_fp8x2_to_halfraw2((__nv_fp8x2_storage_t)(v[k] & 0xFFFFu), __NV_E4M3);
        __half2_raw h1 = __nv_cvt_fp8x2_to_halfraw2((__nv_fp8x2_storage_t)(v[k] >> 16), __NV_E4M3);
        acc[2 * k + 0] = __hfma2(*(__half2*)&h0, w, acc[2 * k + 0]);
        acc[2 * k + 1] = __hfma2(*(__half2*)&h1, w, acc[2 * k + 1]);
    }
}
__device__ __forceinline__ void h2tof(const __half2* acc, float* f) {
#pragma unroll
    for (int k = 0; k < 8; k++) {
        float2 t = __half22float2(acc[k]);
        f[2 * k] = t.x;
        f[2 * k + 1] = t.y;
    }
}

__device__ __forceinline__ unsigned pack_fp8x4(float a, float b, float c, float d) {
    unsigned short p0 = __nv_cvt_float2_to_fp8x2(make_float2(a, b), __NV_SATFINITE, __NV_E4M3);
    unsigned short p1 = __nv_cvt_float2_to_fp8x2(make_float2(c, d), __NV_SATFINITE, __NV_E4M3);
    return (unsigned)p0 | ((unsigned)p1 << 16);
}

// ---------------- CSR build + degree sort ----------------
__global__ void k_cnt_zero(int n) {
    int i = blockIdx.x * blockDim.x + threadIdx.x;
    if (i == 0) g_tot = 0;
    if (i < DBINS) g_dbin[i] = 0;
    if (i < n) g_cnt[i] = 0;
}
__global__ void k_hist(const int* __restrict__ dst, int e) {
    int i = blockIdx.x * blockDim.x + threadIdx.x;
    if (i < e) atomicAdd(&g_cnt[dst[i]], 1);
}
__global__ void k_off(int n) {
    int i = blockIdx.x * blockDim.x + threadIdx.x;
    if (i >= n) return;
    int c = g_cnt[i];
    int p = atomicAdd(&g_tot, c);
    g_off[i] = p;
    g_cur[i] = p;
    g_dinv[i] = rsqrtf((float)(c + 1));
    atomicAdd(&g_dbin[min(c, DBINS - 1)], 1);
}
__global__ void k_dscan() {   // 1 block, exclusive prefix over 64 bins
    if (threadIdx.x == 0) {
        int run = 0;
        for (int i = 0; i < DBINS; i++) {
            int c = g_dbin[i];
            g_dcur[i] = run;
            run += c;
        }
    }
}
__global__ void k_dorder(int n) {
    int i = blockIdx.x * blockDim.x + threadIdx.x;
    if (i >= n) return;
    int b = min(g_cnt[i], DBINS - 1);
    int pos = atomicAdd(&g_dcur[b], 1);
    g_order[pos] = i;
}
__global__ void k_fill(const int* __restrict__ src, const int* __restrict__ dst, int e) {
    int i = blockIdx.x * blockDim.x + threadIdx.x;
    if (i >= e) return;
    int d = dst[i];
    int p = atomicAdd(&g_cur[d], 1);
    g_es[p] = src[i];
}

// ---------------- register-tiled GEMM (FFMA2 inner loop): Y = X @ W, fp8 out -------
template <int K, int J, int SD, bool SCALE>
__global__ __launch_bounds__(256)
void k_gemm(const float* __restrict__ X, const float* __restrict__ W,
            unsigned char* __restrict__ Y, const float* __restrict__ asv,
            const float* __restrict__ adv, int n) {
    __shared__ float Ws[K * J];
    __shared__ float Xs[32 * 128];
    const int JT = J / 64;
    int tid = threadIdx.x;
    int tx = tid & 15, ty = tid >> 4;
    int row0 = blockIdx.x * 128;

    for (int i = tid; i < K * J / 4; i += 256)
        ((float4*)Ws)[i] = ((const float4*)W)[i];

    unsigned long long acc2[JT][8][2];
#pragma unroll
    for (int jc = 0; jc < JT; jc++)
#pragma unroll
        for (int i = 0; i < 8; i++) {
            acc2[jc][i][0] = 0ull;
            acc2[jc][i][1] = 0ull;
        }

    for (int k0 = 0; k0 < K; k0 += 32) {
        __syncthreads();
#pragma unroll
        for (int it = 0; it < 4; it++) {
            int i = tid + it * 256;
            int r = i >> 3, c4 = i & 7;
            int gr = row0 + r;
            float4 v = make_float4(0.f, 0.f, 0.f, 0.f);
            if (gr < n) v = ((const float4*)X)[(size_t)gr * (K / 4) + (k0 >> 2) + c4];
            int kk = c4 * 4;
            Xs[(kk + 0) * 128 + r] = v.x;
            Xs[(kk + 1) * 128 + r] = v.y;
            Xs[(kk + 2) * 128 + r] = v.z;
            Xs[(kk + 3) * 128 + r] = v.w;
        }
        __syncthreads();
#pragma unroll
        for (int kk = 0; kk < 32; kk++) {
            float xr[8];
            *(float4*)xr = *(const float4*)(Xs + kk * 128 + ty * 8);
            *(float4*)(xr + 4) = *(const float4*)(Xs + kk * 128 + ty * 8 + 4);
            unsigned long long xp[8];
#pragma unroll
            for (int i = 0; i < 8; i++) xp[i] = pack_dup(xr[i]);
#pragma unroll
            for (int jc = 0; jc < JT; jc++) {
                ulonglong2 w = *(const ulonglong2*)(Ws + (k0 + kk) * J + jc * 64 + tx * 4);
#pragma unroll
                for (int i = 0; i < 8; i++) {
                    ffma2(acc2[jc][i][0], xp[i], w.x);
                    ffma2(acc2[jc][i][1], xp[i], w.y);
                }
            }
        }
    }

    float acc[JT][8][4];
#pragma unroll
    for (int jc = 0; jc < JT; jc++)
#pragma unroll
        for (int i = 0; i < 8; i++) {
            unpack2(acc2[jc][i][0], acc[jc][i][0], acc[jc][i][1]);
            unpack2(acc2[jc][i][1], acc[jc][i][2], acc[jc][i][3]);
        }

#pragma unroll
    for (int i = 0; i < 8; i++) {
        int gr = row0 + ty * 8 + i;
        if (gr >= n) continue;
        float dd = SCALE ? g_dinv[gr] : 1.f;
#pragma unroll
        for (int jc = 0; jc < JT; jc++) {
            unsigned st = pack_fp8x4(dd * acc[jc][i][0], dd * acc[jc][i][1],
                                     dd * acc[jc][i][2], dd * acc[jc][i][3]);
            ((unsigned*)Y)[(size_t)gr * (J / 4) + jc * 16 + tx] = st;
        }
    }

    if (SD == 1) {
        float as[2][4], ad[2][4];
#pragma unroll
        for (int jc = 0; jc < JT; jc++)
#pragma unroll
            for (int c = 0; c < 4; c++) {
                as[jc][c] = asv[jc * 64 + tx * 4 + c];
                ad[jc][c] = adv[jc * 64 + tx * 4 + c];
            }
#pragma unroll
        for (int i = 0; i < 8; i++) {
            float s0 = 0.f, d0 = 0.f, s1 = 0.f, d1 = 0.f;
#pragma unroll
            for (int c = 0; c < 4; c++) {
                s0 += acc[0][i][c] * as[0][c];
                d0 += acc[0][i][c] * ad[0][c];
                s1 += acc[JT - 1][i][c] * as[1][c];
                d1 += acc[JT - 1][i][c] * ad[1][c];
            }
#pragma unroll
            for (int o = 8; o; o >>= 1) {
                s0 += __shfl_xor_sync(FULL, s0, o);
                d0 += __shfl_xor_sync(FULL, d0, o);
                s1 += __shfl_xor_sync(FULL, s1, o);
                d1 += __shfl_xor_sync(FULL, d1, o);
            }
            int gr = row0 + ty * 8 + i;
            if (tx == 0 && gr < n) {
                g_Sv[gr] = make_float2(s0, s1);
                g_Dv[gr] = make_float2(d0, d1);
            }
        }
    } else if (SD == 2) {
        float as[4], ad[4];
        int h = tx >> 3;
#pragma unroll
        for (int c = 0; c < 4; c++) {
            as[c] = asv[h * 32 + (tx & 7) * 4 + c];
            ad[c] = adv[h * 32 + (tx & 7) * 4 + c];
        }
#pragma unroll
        for (int i = 0; i < 8; i++) {
            float s = 0.f, d = 0.f;
#pragma unroll
            for (int c = 0; c < 4; c++) {
                s += acc[0][i][c] * as[c];
                d += acc[0][i][c] * ad[c];
            }
#pragma unroll
            for (int o = 4; o; o >>= 1) {
                s += __shfl_xor_sync(FULL, s, o);
                d += __shfl_xor_sync(FULL, d, o);
            }
            int gr = row0 + ty * 8 + i;
            if ((tx & 7) == 0 && gr < n) {
                ((float*)g_Sv)[gr * 2 + h] = s;
                ((float*)g_Dv)[gr * 2 + h] = d;
            }
        }
    }
}

// ---------------- GCN: 4 lanes/node (degree-ordered), fp8 rows, half2 accumulation -
template <bool PRESCALED>
__global__ __launch_bounds__(160)
void k_gcn_node(const unsigned char* __restrict__ T, const float* __restrict__ b,
                float* __restrict__ X, const int* __restrict__ order, int n) {
    int g = blockIdx.x * blockDim.x + threadIdx.x;
    int wi = g >> 2;
    int lane = threadIdx.x & 3;
    unsigned gmask = 0xFu << ((threadIdx.x & 31) & ~3);
    if (wi >= n) return;   // subgroup exits together; mask stays valid
    int w = __ldg(order + wi);
    const uint4* T4 = (const uint4*)T;   // row = 64 fp8 = 4 uint4
    float dw = g_dinv[w];
    const __half2 ONE2 = __float2half2_rn(1.f);
    __half2 acch[8];
#pragma unroll
    for (int i = 0; i < 8; i++) acch[i] = __float2half2_rn(0.f);
    acc16h(T4, (size_t)w * 4 + lane, PRESCALED ? ONE2 : __float2half2_rn(dw), acch);
    int beg = g_off[w], end = beg + g_cnt[w];
    for (int base = beg; base < end; base += 4) {
        int j = base + lane;
        int sj = w; float cj = 0.f;
        if (j < end) { sj = g_es[j]; cj = PRESCALED ? 1.f : g_dinv[sj]; }
        int cnt = min(4, end - base);
        for (int t = 0; t < cnt; t++) {
            int s = __shfl_sync(gmask, sj, t, 4);
            __half2 c2 = ONE2;
            if (!PRESCALED) {
                float c = __shfl_sync(gmask, cj, t, 4);
                c2 = __float2half2_rn(c);
            }
            acc16h(T4, (size_t)s * 4 + lane, c2, acch);
        }
    }
    float acc[16];
    h2tof(acch, acc);
#pragma unroll
    for (int k = 0; k < 4; k++) {
        float4 bb = ((const float4*)b)[lane * 4 + k];
        float4 o;
        o.x = fmaxf(dw * acc[4 * k + 0] + bb.x, 0.f);
        o.y = fmaxf(dw * acc[4 * k + 1] + bb.y, 0.f);
        o.z = fmaxf(dw * acc[4 * k + 2] + bb.z, 0.f);
        o.w = fmaxf(dw * acc[4 * k + 3] + bb.w, 0.f);
        ((float4*)X)[(size_t)w * 16 + lane * 4 + k] = o;
    }
}

// ---------------- fused GAT layer: SUBW lanes/node (degree-ordered), fp8 rows ------
template <int CH, bool CONCAT>
__global__ void k_gat_node(const unsigned char* __restrict__ T,
                           const float* __restrict__ bias,
                           float* __restrict__ X, float* __restrict__ out,
                           const int* __restrict__ order, int n) {
    constexpr int SUBW = (CH == 64) ? 8 : 4;   // row = 2*CH fp8 = SUBW uint4
    int g = blockIdx.x * blockDim.x + threadIdx.x;
    int wi = g / SUBW;
    int lane = threadIdx.x & (SUBW - 1);
    unsigned gmask = (SUBW == 8) ? (0xFFu << ((threadIdx.x & 31) & ~7))
                                 : (0xFu << ((threadIdx.x & 31) & ~3));
    if (wi >= n) return;   // subgroup exits together
    int w = __ldg(order + wi);
    float2 Dd = g_Dv[w];
    float2 Sw = g_Sv[w];
    float self0 = lrelu(Sw.x + Dd.x);
    float self1 = lrelu(Sw.y + Dd.y);
    int beg = g_off[w], end = beg + g_cnt[w];

    // --- pass 1: online max+sum over incoming scores, cache raw scores ---
    float m0 = (lane == 0) ? self0 : -1e30f;
    float m1 = (lane == 0) ? self1 : -1e30f;
    float z0 = (lane == 0) ? 1.f : 0.f;
    float z1 = (lane == 0) ? 1.f : 0.f;
    for (int j = beg + lane; j < end; j += SUBW) {
        float2 sv = g_Sv[g_es[j]];
        float e0 = lrelu(sv.x + Dd.x);
        float e1 = lrelu(sv.y + Dd.y);
        g_eb[j] = make_float2(e0, e1);
        if (e0 > m0) { z0 = z0 * __expf(m0 - e0) + 1.f; m0 = e0; }
        else           z0 += __expf(e0 - m0);
        if (e1 > m1) { z1 = z1 * __expf(m1 - e1) + 1.f; m1 = e1; }
        else           z1 += __expf(e1 - m1);
    }
#pragma unroll
    for (int o = SUBW / 2; o; o >>= 1) {
        float om = __shfl_xor_sync(gmask, m0, o, SUBW);
        float oz = __shfl_xor_sync(gmask, z0, o, SUBW);
        float M = fmaxf(m0, om);
        z0 = z0 * __expf(m0 - M) + oz * __expf(om - M);
        m0 = M;
        om = __shfl_xor_sync(gmask, m1, o, SUBW);
        oz = __shfl_xor_sync(gmask, z1, o, SUBW);
        M = fmaxf(m1, om);
        z1 = z1 * __expf(m1 - M) + oz * __expf(om - M);
        m1 = M;
    }
    float iz0 = 1.f / (z0 + 1e-16f);
    float iz1 = 1.f / (z1 + 1e-16f);

    // --- pass 2: weighted feature accumulate (half2 HFMA2) ---
    const uint4* T4 = (const uint4*)T;
    int hh = (lane >= SUBW / 2);
    __half2 acch[8];
#pragma unroll
    for (int i = 0; i < 8; i++) acch[i] = __float2half2_rn(0.f);
    float wself = hh ? __expf(self1 - m1) * iz1 : __expf(self0 - m0) * iz0;
    acc16h(T4, (size_t)w * SUBW + lane, __float2half2_rn(wself), acch);
    for (int base = beg; base < end; base += SUBW) {
        int j = base + lane;
        int sj = w; float a0 = 0.f, a1 = 0.f;
        if (j < end) {
            sj = g_es[j];
            float2 eb = g_eb[j];
            a0 = __expf(eb.x - m0) * iz0;
            a1 = __expf(eb.y - m1) * iz1;
        }
        int cnt = min(SUBW, end - base);
        for (int t = 0; t < cnt; t++) {
            int s = __shfl_sync(gmask, sj, t, SUBW);
            float wa = __shfl_sync(gmask, a0, t, SUBW);
            float wb = __shfl_sync(gmask, a1, t, SUBW);
            float wgt = hh ? wb : wa;
            acc16h(T4, (size_t)s * SUBW + lane, __float2half2_rn(wgt), acch);
        }
    }
    float acc[16];
    h2tof(acch, acc);

    if (CONCAT) {
#pragma unroll
        for (int k = 0; k < 4; k++) {
            float4 bb = ((const float4*)bias)[lane * 4 + k];
            float4 o;
            o.x = fmaxf(acc[4 * k + 0] + bb.x, 0.f);
            o.y = fmaxf(acc[4 * k + 1] + bb.y, 0.f);
            o.z = fmaxf(acc[4 * k + 2] + bb.z, 0.f);
            o.w = fmaxf(acc[4 * k + 3] + bb.w, 0.f);
            ((float4*)X)[(size_t)w * 32 + lane * 4 + k] = o;
        }
    } else {
        // SUBW=4: lanes 0,1 = head0 ch[lane*16..+15]; lanes 2,3 = head1 same ch.
        float v[16];
        int cl = lane & 1;
#pragma unroll
        for (int i = 0; i < 16; i++) {
            float oth = __shfl_sync(gmask, acc[i], (threadIdx.x & 2) ? (cl) : (cl + 2), 4);
            v[i] = 0.5f * (acc[i] + oth) + bias[cl * 16 + i];
        }
        float mx = v[0];
#pragma unroll
        for (int i = 1; i < 16; i++) mx = fmaxf(mx, v[i]);
        mx = fmaxf(mx, __shfl_xor_sync(gmask, mx, 1, 4));
        float sum = 0.f;
#pragma unroll
        for (int i = 0; i < 16; i++) sum += __expf(v[i] - mx);
        sum += __shfl_xor_sync(gmask, sum, 1, 4);
        float ls = logf(sum);
        if (lane < 2) {
#pragma unroll
            for (int k = 0; k < 4; k++) {
                float4 o;
                o.x = v[4 * k + 0] - mx - ls;
                o.y = v[4 * k + 1] - mx - ls;
                o.z = v[4 * k + 2] - mx - ls;
                o.w = v[4 * k + 3] - mx - ls;
                ((float4*)out)[(size_t)w * 8 + cl * 4 + k] = o;
            }
        }
    }
}

// ---------------- launcher ----------------
static inline int cdiv(long long a, int b) { return (int)((a + b - 1) / b); }

extern "C" void kernel_launch(void* const* d_in, const int* in_sizes, int n_in,
                              void* d_out, int out_size) {
    const float* x   = (const float*)d_in[0];
    const int*   ei  = (const int*)d_in[1];
    const float* W1  = (const float*)d_in[2];
    const float* b1  = (const float*)d_in[3];
    const float* W2  = (const float*)d_in[4];
    const float* b2  = (const float*)d_in[5];
    const float* Wg1 = (const float*)d_in[6];
    const float* as1 = (const float*)d_in[7];
    const float* ad1 = (const float*)d_in[8];
    const float* bg1 = (const float*)d_in[9];
    const float* Wg2 = (const float*)d_in[10];
    const float* as2 = (const float*)d_in[11];
    const float* ad2 = (const float*)d_in[12];
    const float* bg2 = (const float*)d_in[13];

    int n = in_sizes[0] / 128;
    int e = in_sizes[1] / 2;
    const int* src = ei;
    const int* dst = ei + e;

    unsigned char* T = nullptr; cudaGetSymbolAddress((void**)&T, g_bufT);
    float* X = nullptr; cudaGetSymbolAddress((void**)&X, g_bufX);
    int* order = nullptr; cudaGetSymbolAddress((void**)&order, g_order);
    float* out = (float*)d_out;

    static cudaStream_t s1 = nullptr;
    static cudaEvent_t e0 = nullptr, eCsr = nullptr;
    if (!s1) {
        cudaStreamCreateWithFlags(&s1, cudaStreamNonBlocking);
        cudaEventCreateWithFlags(&e0, cudaEventDisableTiming);
        cudaEventCreateWithFlags(&eCsr, cudaEventDisableTiming);
    }

    const int B = 256;
    int quad_blocks = cdiv((long long)n * 4, 160);    // 1250 exact (block=160)
    int oct_blocks  = cdiv((long long)n * 8, 128);    // 3125 exact (block=128)
    int gemm_blocks = cdiv(n, 128);

    // --- fork: CSR build + degree counting-sort on side stream ---
    cudaEventRecord(e0, 0);
    cudaStreamWaitEvent(s1, e0, 0);
    k_cnt_zero<<<cdiv(n, B), B, 0, s1>>>(n);
    k_hist<<<cdiv(e, B), B, 0, s1>>>(dst, e);
    k_off<<<cdiv(n, B), B, 0, s1>>>(n);
    k_dscan<<<1, 32, 0, s1>>>();
    k_dorder<<<cdiv(n, B), B, 0, s1>>>(n);
    k_fill<<<cdiv(e, B), B, 0, s1>>>(src, dst, e);
    cudaEventRecord(eCsr, s1);

    // --- GCN1: 128 -> 64 (no dinv dependency; per-edge dinv in node kernel) ---
    k_gemm<128, 64, 0, false><<<gemm_blocks, 256>>>(x, W1, T, nullptr, nullptr, n);
    cudaStreamWaitEvent(0, eCsr, 0);     // CSR + order ready before aggregation
    k_gcn_node<false><<<quad_blocks, 160>>>(T, b1, X, order, n);

    // --- GCN2: 64 -> 64 (rows pre-scaled by dinv; dinv already synced) ---
    k_gemm<64, 64, 0, true><<<gemm_blocks, 256>>>(X, W2, T, nullptr, nullptr, n);
    k_gcn_node<true><<<quad_blocks, 160>>>(T, b2, X, order, n);

    // --- GAT1: 64 -> 2x64 concat (scores fused into GEMM epilogue) ---
    k_gemm<64, 128, 1, false><<<gemm_blocks, 256>>>(X, Wg1, T, as1, ad1, n);
    k_gat_node<64, true><<<oct_blocks, 128>>>(T, bg1, X, nullptr, order, n);

    // --- GAT2: 128 -> 2x32 mean + log_softmax ---
    k_gemm<128, 64, 2, false><<<gemm_blocks, 256>>>(X, Wg2, T, as2, ad2, n);
    k_gat_node<32, false><<<quad_blocks, 160>>>(T, bg2, nullptr, out, order, n);
}

// round 15
// speedup vs baseline: 1.1104x; 1.1104x over previous
#include <cuda_runtime.h>
#include <cuda_fp16.h>
#include <cuda_fp8.h>

#define NN 50000
#define EE 800000
#define FULL 0xffffffffu
#define SHIFT 30.0f

// ---------------- device scratch ----------------
__device__ __align__(16) unsigned char g_bufT[NN * 128]; // messages, fp8 e4m3 (bytes)
__device__ __align__(16) float g_bufX[NN * 128];         // layer activations (fp32)
__device__ float  g_dinv[NN];
__device__ int    g_cnt[NN];
__device__ int    g_off[NN];
__device__ int    g_cur[NN];
__device__ int    g_tot;
__device__ int    g_es[EE];          // CSR: src ids grouped by dst
__device__ float2 g_Sv[NN];          // per-node per-head <g, a_src>
__device__ float2 g_Dv[NN];          // per-node per-head <g, a_dst>
__device__ float2 g_eb[EE];          // cached per-edge exp(score-SHIFT) (2 heads)

// ---------------- helpers ----------------
__device__ __forceinline__ float lrelu(float x) { return x > 0.f ? x : 0.2f * x; }

// packed f32x2 FMA: d = a*b + d (bit-exact 2x FFMA, Blackwell FFMA2)
__device__ __forceinline__ void ffma2(unsigned long long& d, unsigned long long a,
                                      unsigned long long b) {
    asm("fma.rn.f32x2 %0, %1, %2, %0;" : "+l"(d) : "l"(a), "l"(b));
}
__device__ __forceinline__ unsigned long long pack_dup(float x) {
    unsigned long long r;
    asm("mov.b64 %0, {%1, %1};" : "=l"(r) : "r"(__float_as_uint(x)));
    return r;
}
__device__ __forceinline__ void unpack2(unsigned long long v, float& lo, float& hi) {
    unsigned a, b;
    asm("mov.b64 {%0, %1}, %2;" : "=r"(a), "=r"(b) : "l"(v));
    lo = __uint_as_float(a);
    hi = __uint_as_float(b);
}

// fp8 gather with half2 HFMA2 accumulation: 1 LDG + 8 cvt + 8 HFMA2 per 16 channels
__device__ __forceinline__ void acc16h(const uint4* __restrict__ base, size_t idx,
                                       __half2 w, __half2* acc) {
    uint4 q = __ldg(base + idx);
    unsigned v[4] = {q.x, q.y, q.z, q.w};
#pragma unroll
    for (int k = 0; k < 4; k++) {
        __half2_raw h0 = __nv_cvt_fp8x2_to_halfraw2((__nv_fp8x2_storage_t)(v[k] & 0xFFFFu), __NV_E4M3);
        __half2_raw h1 = __nv_cvt_fp8x2_to_halfraw2((__nv_fp8x2_storage_t)(v[k] >> 16), __NV_E4M3);
        acc[2 * k + 0] = __hfma2(*(__half2*)&h0, w, acc[2 * k + 0]);
        acc[2 * k + 1] = __hfma2(*(__half2*)&h1, w, acc[2 * k + 1]);
    }
}
__device__ __forceinline__ void h2tof(const __half2* acc, float* f) {
#pragma unroll
    for (int k = 0; k < 8; k++) {
        float2 t = __half22float2(acc[k]);
        f[2 * k] = t.x;
        f[2 * k + 1] = t.y;
    }
}

__device__ __forceinline__ unsigned pack_fp8x4(float a, float b, float c, float d) {
    unsigned short p0 = __nv_cvt_float2_to_fp8x2(make_float2(a, b), __NV_SATFINITE, __NV_E4M3);
    unsigned short p1 = __nv_cvt_float2_to_fp8x2(make_float2(c, d), __NV_SATFINITE, __NV_E4M3);
    return (unsigned)p0 | ((unsigned)p1 << 16);
}

// ---------------- CSR build ----------------
__global__ void k_cnt_zero(int n) {
    int i = blockIdx.x * blockDim.x + threadIdx.x;
    if (i == 0) g_tot = 0;
    if (i < n) g_cnt[i] = 0;
}
__global__ void k_hist(const int* __restrict__ dst, int e) {
    int i = blockIdx.x * blockDim.x + threadIdx.x;
    if (i < e) atomicAdd(&g_cnt[dst[i]], 1);
}
__global__ void k_off(int n) {
    int i = blockIdx.x * blockDim.x + threadIdx.x;
    if (i >= n) return;
    int c = g_cnt[i];
    int p = atomicAdd(&g_tot, c);
    g_off[i] = p;
    g_cur[i] = p;
    g_dinv[i] = rsqrtf((float)(c + 1));
}
__global__ void k_fill(const int* __restrict__ src, const int* __restrict__ dst, int e) {
    int i = blockIdx.x * blockDim.x + threadIdx.x;
    if (i >= e) return;
    int d = dst[i];
    int p = atomicAdd(&g_cur[d], 1);
    g_es[p] = src[i];
}

// ---------------- register-tiled GEMM (FFMA2 inner loop): Y = X @ W, fp8 out -------
template <int K, int J, int SD, bool SCALE>
__global__ __launch_bounds__(256)
void k_gemm(const float* __restrict__ X, const float* __restrict__ W,
            unsigned char* __restrict__ Y, const float* __restrict__ asv,
            const float* __restrict__ adv, int n) {
    __shared__ float Ws[K * J];
    __shared__ float Xs[32 * 128];
    const int JT = J / 64;
    int tid = threadIdx.x;
    int tx = tid & 15, ty = tid >> 4;
    int row0 = blockIdx.x * 128;

    for (int i = tid; i < K * J / 4; i += 256)
        ((float4*)Ws)[i] = ((const float4*)W)[i];

    unsigned long long acc2[JT][8][2];
#pragma unroll
    for (int jc = 0; jc < JT; jc++)
#pragma unroll
        for (int i = 0; i < 8; i++) {
            acc2[jc][i][0] = 0ull;
            acc2[jc][i][1] = 0ull;
        }

    for (int k0 = 0; k0 < K; k0 += 32) {
        __syncthreads();
#pragma unroll
        for (int it = 0; it < 4; it++) {
            int i = tid + it * 256;
            int r = i >> 3, c4 = i & 7;
            int gr = row0 + r;
            float4 v = make_float4(0.f, 0.f, 0.f, 0.f);
            if (gr < n) v = ((const float4*)X)[(size_t)gr * (K / 4) + (k0 >> 2) + c4];
            int kk = c4 * 4;
            Xs[(kk + 0) * 128 + r] = v.x;
            Xs[(kk + 1) * 128 + r] = v.y;
            Xs[(kk + 2) * 128 + r] = v.z;
            Xs[(kk + 3) * 128 + r] = v.w;
        }
        __syncthreads();
#pragma unroll
        for (int kk = 0; kk < 32; kk++) {
            float xr[8];
            *(float4*)xr = *(const float4*)(Xs + kk * 128 + ty * 8);
            *(float4*)(xr + 4) = *(const float4*)(Xs + kk * 128 + ty * 8 + 4);
            unsigned long long xp[8];
#pragma unroll
            for (int i = 0; i < 8; i++) xp[i] = pack_dup(xr[i]);
#pragma unroll
            for (int jc = 0; jc < JT; jc++) {
                ulonglong2 w = *(const ulonglong2*)(Ws + (k0 + kk) * J + jc * 64 + tx * 4);
#pragma unroll
                for (int i = 0; i < 8; i++) {
                    ffma2(acc2[jc][i][0], xp[i], w.x);
                    ffma2(acc2[jc][i][1], xp[i], w.y);
                }
            }
        }
    }

    float acc[JT][8][4];
#pragma unroll
    for (int jc = 0; jc < JT; jc++)
#pragma unroll
        for (int i = 0; i < 8; i++) {
            unpack2(acc2[jc][i][0], acc[jc][i][0], acc[jc][i][1]);
            unpack2(acc2[jc][i][1], acc[jc][i][2], acc[jc][i][3]);
        }

#pragma unroll
    for (int i = 0; i < 8; i++) {
        int gr = row0 + ty * 8 + i;
        if (gr >= n) continue;
        float dd = SCALE ? g_dinv[gr] : 1.f;
#pragma unroll
        for (int jc = 0; jc < JT; jc++) {
            unsigned st = pack_fp8x4(dd * acc[jc][i][0], dd * acc[jc][i][1],
                                     dd * acc[jc][i][2], dd * acc[jc][i][3]);
            ((unsigned*)Y)[(size_t)gr * (J / 4) + jc * 16 + tx] = st;
        }
    }

    if (SD == 1) {
        float as[2][4], ad[2][4];
#pragma unroll
        for (int jc = 0; jc < JT; jc++)
#pragma unroll
            for (int c = 0; c < 4; c++) {
                as[jc][c] = asv[jc * 64 + tx * 4 + c];
                ad[jc][c] = adv[jc * 64 + tx * 4 + c];
            }
#pragma unroll
        for (int i = 0; i < 8; i++) {
            float s0 = 0.f, d0 = 0.f, s1 = 0.f, d1 = 0.f;
#pragma unroll
            for (int c = 0; c < 4; c++) {
                s0 += acc[0][i][c] * as[0][c];
                d0 += acc[0][i][c] * ad[0][c];
                s1 += acc[JT - 1][i][c] * as[1][c];
                d1 += acc[JT - 1][i][c] * ad[1][c];
            }
#pragma unroll
            for (int o = 8; o; o >>= 1) {
                s0 += __shfl_xor_sync(FULL, s0, o);
                d0 += __shfl_xor_sync(FULL, d0, o);
                s1 += __shfl_xor_sync(FULL, s1, o);
                d1 += __shfl_xor_sync(FULL, d1, o);
            }
            int gr = row0 + ty * 8 + i;
            if (tx == 0 && gr < n) {
                g_Sv[gr] = make_float2(s0, s1);
                g_Dv[gr] = make_float2(d0, d1);
            }
        }
    } else if (SD == 2) {
        float as[4], ad[4];
        int h = tx >> 3;
#pragma unroll
        for (int c = 0; c < 4; c++) {
            as[c] = asv[h * 32 + (tx & 7) * 4 + c];
            ad[c] = adv[h * 32 + (tx & 7) * 4 + c];
        }
#pragma unroll
        for (int i = 0; i < 8; i++) {
            float s = 0.f, d = 0.f;
#pragma unroll
            for (int c = 0; c < 4; c++) {
                s += acc[0][i][c] * as[c];
                d += acc[0][i][c] * ad[c];
            }
#pragma unroll
            for (int o = 4; o; o >>= 1) {
                s += __shfl_xor_sync(FULL, s, o);
                d += __shfl_xor_sync(FULL, d, o);
            }
            int gr = row0 + ty * 8 + i;
            if ((tx & 7) == 0 && gr < n) {
                ((float*)g_Sv)[gr * 2 + h] = s;
                ((float*)g_Dv)[gr * 2 + h] = d;
            }
        }
    }
}

// ---------------- GCN: 4 lanes/node, fp8 rows, half2 accumulation ------------------
template <bool PRESCALED>
__global__ __launch_bounds__(160)
void k_gcn_node(const unsigned char* __restrict__ T, const float* __restrict__ b,
                float* __restrict__ X, int n) {
    int g = blockIdx.x * blockDim.x + threadIdx.x;
    int w = g >> 2;
    int lane = threadIdx.x & 3;
    unsigned gmask = 0xFu << ((threadIdx.x & 31) & ~3);
    if (w >= n) return;   // subgroup exits together; mask stays valid
    const uint4* T4 = (const uint4*)T;   // row = 64 fp8 = 4 uint4
    float dw = g_dinv[w];
    const __half2 ONE2 = __float2half2_rn(1.f);
    __half2 acch[8];
#pragma unroll
    for (int i = 0; i < 8; i++) acch[i] = __float2half2_rn(0.f);
    acc16h(T4, (size_t)w * 4 + lane, PRESCALED ? ONE2 : __float2half2_rn(dw), acch);
    int beg = g_off[w], end = beg + g_cnt[w];
    for (int base = beg; base < end; base += 4) {
        int j = base + lane;
        int sj = w;
        unsigned cpk = 0;
        if (j < end) {
            sj = g_es[j];
            if (!PRESCALED) {
                __half2 c2 = __float2half2_rn(g_dinv[sj]);
                cpk = *(unsigned*)&c2;
            }
        }
        int cnt = min(4, end - base);
        for (int t = 0; t < cnt; t++) {
            int s = __shfl_sync(gmask, sj, t, 4);
            __half2 c2v = ONE2;
            if (!PRESCALED) {
                unsigned cc = __shfl_sync(gmask, cpk, t, 4);
                c2v = *(__half2*)&cc;
            }
            acc16h(T4, (size_t)s * 4 + lane, c2v, acch);
        }
    }
    float acc[16];
    h2tof(acch, acc);
#pragma unroll
    for (int k = 0; k < 4; k++) {
        float4 bb = ((const float4*)b)[lane * 4 + k];
        float4 o;
        o.x = fmaxf(dw * acc[4 * k + 0] + bb.x, 0.f);
        o.y = fmaxf(dw * acc[4 * k + 1] + bb.y, 0.f);
        o.z = fmaxf(dw * acc[4 * k + 2] + bb.z, 0.f);
        o.w = fmaxf(dw * acc[4 * k + 3] + bb.w, 0.f);
        ((float4*)X)[(size_t)w * 16 + lane * 4 + k] = o;
    }
}

// ---------------- fused GAT layer: constant-shift softmax, fp8 rows ----------------
template <int CH, bool CONCAT>
__global__ void k_gat_node(const unsigned char* __restrict__ T,
                           const float* __restrict__ bias,
                           float* __restrict__ X, float* __restrict__ out, int n) {
    constexpr int SUBW = (CH == 64) ? 8 : 4;   // row = 2*CH fp8 = SUBW uint4
    int g = blockIdx.x * blockDim.x + threadIdx.x;
    int w = g / SUBW;
    int lane = threadIdx.x & (SUBW - 1);
    unsigned gmask = (SUBW == 8) ? (0xFFu << ((threadIdx.x & 31) & ~7))
                                 : (0xFu << ((threadIdx.x & 31) & ~3));
    if (w >= n) return;   // subgroup exits together
    float2 Dd = g_Dv[w];
    float2 Sw = g_Sv[w];
    float wself0 = __expf(lrelu(Sw.x + Dd.x) - SHIFT);
    float wself1 = __expf(lrelu(Sw.y + Dd.y) - SHIFT);
    int beg = g_off[w], end = beg + g_cnt[w];

    // --- pass 1: z = sum of exp(score - SHIFT); cache exp terms sequentially ---
    float z0 = (lane == 0) ? wself0 : 0.f;
    float z1 = (lane == 0) ? wself1 : 0.f;
    for (int j = beg + lane; j < end; j += SUBW) {
        float2 sv = g_Sv[g_es[j]];
        float w0 = __expf(lrelu(sv.x + Dd.x) - SHIFT);
        float w1 = __expf(lrelu(sv.y + Dd.y) - SHIFT);
        g_eb[j] = make_float2(w0, w1);
        z0 += w0;
        z1 += w1;
    }
#pragma unroll
    for (int o = SUBW / 2; o; o >>= 1) {
        z0 += __shfl_xor_sync(gmask, z0, o, SUBW);
        z1 += __shfl_xor_sync(gmask, z1, o, SUBW);
    }
    float iz0 = 1.f / z0;
    float iz1 = 1.f / z1;

    // --- pass 2: weighted feature accumulate; weights pre-packed as half2 ----------
    const uint4* T4 = (const uint4*)T;
    int hh = (lane >= SUBW / 2);
    __half2 acch[8];
#pragma unroll
    for (int i = 0; i < 8; i++) acch[i] = __float2half2_rn(0.f);
    float wself = hh ? wself1 * iz1 : wself0 * iz0;
    acc16h(T4, (size_t)w * SUBW + lane, __float2half2_rn(wself), acch);
    for (int base = beg; base < end; base += SUBW) {
        int j = base + lane;
        int sj = w;
        unsigned apk = 0;
        if (j < end) {
            sj = g_es[j];
            float2 eb = g_eb[j];
            __half2 ah = __halves2half2(__float2half_rn(eb.x * iz0),
                                        __float2half_rn(eb.y * iz1));
            apk = *(unsigned*)&ah;
        }
        int cnt = min(SUBW, end - base);
        for (int t = 0; t < cnt; t++) {
            int s = __shfl_sync(gmask, sj, t, SUBW);
            unsigned ap = __shfl_sync(gmask, apk, t, SUBW);
            __half2 a2 = *(__half2*)&ap;
            __half2 w2 = hh ? __high2half2(a2) : __low2half2(a2);
            acc16h(T4, (size_t)s * SUBW + lane, w2, acch);
        }
    }
    float acc[16];
    h2tof(acch, acc);

    if (CONCAT) {
#pragma unroll
        for (int k = 0; k < 4; k++) {
            float4 bb = ((const float4*)bias)[lane * 4 + k];
            float4 o;
            o.x = fmaxf(acc[4 * k + 0] + bb.x, 0.f);
            o.y = fmaxf(acc[4 * k + 1] + bb.y, 0.f);
            o.z = fmaxf(acc[4 * k + 2] + bb.z, 0.f);
            o.w = fmaxf(acc[4 * k + 3] + bb.w, 0.f);
            ((float4*)X)[(size_t)w * 32 + lane * 4 + k] = o;
        }
    } else {
        // SUBW=4: lanes 0,1 = head0 ch[lane*16..+15]; lanes 2,3 = head1 same ch.
        float v[16];
        int cl = lane & 1;
#pragma unroll
        for (int i = 0; i < 16; i++) {
            float oth = __shfl_sync(gmask, acc[i], (threadIdx.x & 2) ? (cl) : (cl + 2), 4);
            v[i] = 0.5f * (acc[i] + oth) + bias[cl * 16 + i];
        }
        float mx = v[0];
#pragma unroll
        for (int i = 1; i < 16; i++) mx = fmaxf(mx, v[i]);
        mx = fmaxf(mx, __shfl_xor_sync(gmask, mx, 1, 4));
        float sum = 0.f;
#pragma unroll
        for (int i = 0; i < 16; i++) sum += __expf(v[i] - mx);
        sum += __shfl_xor_sync(gmask, sum, 1, 4);
        float ls = logf(sum);
        if (lane < 2) {
#pragma unroll
            for (int k = 0; k < 4; k++) {
                float4 o;
                o.x = v[4 * k + 0] - mx - ls;
                o.y = v[4 * k + 1] - mx - ls;
                o.z = v[4 * k + 2] - mx - ls;
                o.w = v[4 * k + 3] - mx - ls;
                ((float4*)out)[(size_t)w * 8 + cl * 4 + k] = o;
            }
        }
    }
}

// ---------------- launcher ----------------
static inline int cdiv(long long a, int b) { return (int)((a + b - 1) / b); }

extern "C" void kernel_launch(void* const* d_in, const int* in_sizes, int n_in,
                              void* d_out, int out_size) {
    const float* x   = (const float*)d_in[0];
    const int*   ei  = (const int*)d_in[1];
    const float* W1  = (const float*)d_in[2];
    const float* b1  = (const float*)d_in[3];
    const float* W2  = (const float*)d_in[4];
    const float* b2  = (const float*)d_in[5];
    const float* Wg1 = (const float*)d_in[6];
    const float* as1 = (const float*)d_in[7];
    const float* ad1 = (const float*)d_in[8];
    const float* bg1 = (const float*)d_in[9];
    const float* Wg2 = (const float*)d_in[10];
    const float* as2 = (const float*)d_in[11];
    const float* ad2 = (const float*)d_in[12];
    const float* bg2 = (const float*)d_in[13];

    int n = in_sizes[0] / 128;
    int e = in_sizes[1] / 2;
    const int* src = ei;
    const int* dst = ei + e;

    unsigned char* T = nullptr; cudaGetSymbolAddress((void**)&T, g_bufT);
    float* X = nullptr; cudaGetSymbolAddress((void**)&X, g_bufX);
    float* out = (float*)d_out;

    static cudaStream_t s1 = nullptr;
    static cudaEvent_t e0 = nullptr, eCsr = nullptr;
    if (!s1) {
        cudaStreamCreateWithFlags(&s1, cudaStreamNonBlocking);
        cudaEventCreateWithFlags(&e0, cudaEventDisableTiming);
        cudaEventCreateWithFlags(&eCsr, cudaEventDisableTiming);
    }

    const int B = 256;
    int quad_blocks = cdiv((long long)n * 4, 160);    // 1250 exact (block=160)
    int oct_blocks  = cdiv((long long)n * 8, 128);    // 3125 exact (block=128)
    int gemm_blocks = cdiv(n, 128);

    // --- fork: CSR build on side stream (fully overlapped with GEMM1) ---
    cudaEventRecord(e0, 0);
    cudaStreamWaitEvent(s1, e0, 0);
    k_cnt_zero<<<cdiv(n, B), B, 0, s1>>>(n);
    k_hist<<<cdiv(e, B), B, 0, s1>>>(dst, e);
    k_off<<<cdiv(n, B), B, 0, s1>>>(n);
    k_fill<<<cdiv(e, B), B, 0, s1>>>(src, dst, e);
    cudaEventRecord(eCsr, s1);

    // --- GCN1: 128 -> 64 (no dinv dependency; per-edge dinv in node kernel) ---
    k_gemm<128, 64, 0, false><<<gemm_blocks, 256>>>(x, W1, T, nullptr, nullptr, n);
    cudaStreamWaitEvent(0, eCsr, 0);     // CSR + dinv ready before aggregation
    k_gcn_node<false><<<quad_blocks, 160>>>(T, b1, X, n);

    // --- GCN2: 64 -> 64 (rows pre-scaled by dinv; dinv already synced) ---
    k_gemm<64, 64, 0, true><<<gemm_blocks, 256>>>(X, W2, T, nullptr, nullptr, n);
    k_gcn_node<true><<<quad_blocks, 160>>>(T, b2, X, n);

    // --- GAT1: 64 -> 2x64 concat (scores fused into GEMM epilogue) ---
    k_gemm<64, 128, 1, false><<<gemm_blocks, 256>>>(X, Wg1, T, as1, ad1, n);
    k_gat_node<64, true><<<oct_blocks, 128>>>(T, bg1, X, nullptr, n);

    // --- GAT2: 128 -> 2x32 mean + log_softmax ---
    k_gemm<128, 64, 2, false><<<gemm_blocks, 256>>>(X, Wg2, T, as2, ad2, n);
    k_gat_node<32, false><<<quad_blocks, 160>>>(T, bg2, nullptr, out, n);
}

// round 16
// speedup vs baseline: 1.3074x; 1.1774x over previous
#include <cuda_runtime.h>
#include <cuda_fp16.h>
#include <cuda_fp8.h>

#define NN 50000
#define EE 800000
#define FULL 0xffffffffu
#define SHIFT 30.0f

// ---------------- device scratch ----------------
__device__ __align__(16) unsigned char g_bufT[NN * 128]; // messages, fp8 e4m3 (bytes)
__device__ __align__(16) float g_bufX[NN * 128];         // layer activations (fp32)
__device__ float  g_dinv[NN];
__device__ int    g_cnt[NN];
__device__ int    g_off[NN];
__device__ int    g_cur[NN];
__device__ int    g_tot;
__device__ int    g_es[EE];          // CSR: src ids grouped by dst
__device__ float2 g_Sv[NN];          // per-node per-head <g, a_src>
__device__ float2 g_Dv[NN];          // per-node per-head <g, a_dst>
__device__ float2 g_eb[EE];          // cached per-edge exp(score-SHIFT) (2 heads)

// ---------------- helpers ----------------
__device__ __forceinline__ float lrelu(float x) { return x > 0.f ? x : 0.2f * x; }

// fp8 gather with half2 HFMA2 accumulation: 1 LDG + 8 cvt + 8 HFMA2 per 16 channels
__device__ __forceinline__ void acc16h(const uint4* __restrict__ base, size_t idx,
                                       __half2 w, __half2* acc) {
    uint4 q = __ldg(base + idx);
    unsigned v[4] = {q.x, q.y, q.z, q.w};
#pragma unroll
    for (int k = 0; k < 4; k++) {
        __half2_raw h0 = __nv_cvt_fp8x2_to_halfraw2((__nv_fp8x2_storage_t)(v[k] & 0xFFFFu), __NV_E4M3);
        __half2_raw h1 = __nv_cvt_fp8x2_to_halfraw2((__nv_fp8x2_storage_t)(v[k] >> 16), __NV_E4M3);
        acc[2 * k + 0] = __hfma2(*(__half2*)&h0, w, acc[2 * k + 0]);
        acc[2 * k + 1] = __hfma2(*(__half2*)&h1, w, acc[2 * k + 1]);
    }
}
__device__ __forceinline__ void h2tof(const __half2* acc, float* f) {
#pragma unroll
    for (int k = 0; k < 8; k++) {
        float2 t = __half22float2(acc[k]);
        f[2 * k] = t.x;
        f[2 * k + 1] = t.y;
    }
}

__device__ __forceinline__ unsigned pack_fp8x4(float a, float b, float c, float d) {
    unsigned short p0 = __nv_cvt_float2_to_fp8x2(make_float2(a, b), __NV_SATFINITE, __NV_E4M3);
    unsigned short p1 = __nv_cvt_float2_to_fp8x2(make_float2(c, d), __NV_SATFINITE, __NV_E4M3);
    return (unsigned)p0 | ((unsigned)p1 << 16);
}

__device__ __forceinline__ void mma16816(float* c, unsigned a0, unsigned a1,
                                         unsigned a2, unsigned a3,
                                         unsigned b0, unsigned b1) {
    asm volatile(
        "mma.sync.aligned.m16n8k16.row.col.f32.f16.f16.f32 "
        "{%0,%1,%2,%3}, {%4,%5,%6,%7}, {%8,%9}, {%0,%1,%2,%3};"
        : "+f"(c[0]), "+f"(c[1]), "+f"(c[2]), "+f"(c[3])
        : "r"(a0), "r"(a1), "r"(a2), "r"(a3), "r"(b0), "r"(b1));
}

// ---------------- CSR build ----------------
__global__ void k_cnt_zero(int n) {
    int i = blockIdx.x * blockDim.x + threadIdx.x;
    if (i == 0) g_tot = 0;
    if (i < n) g_cnt[i] = 0;
}
__global__ void k_hist(const int* __restrict__ dst, int e) {
    int i = blockIdx.x * blockDim.x + threadIdx.x;
    if (i < e) atomicAdd(&g_cnt[dst[i]], 1);
}
__global__ void k_off(int n) {
    int i = blockIdx.x * blockDim.x + threadIdx.x;
    if (i >= n) return;
    int c = g_cnt[i];
    int p = atomicAdd(&g_tot, c);
    g_off[i] = p;
    g_cur[i] = p;
    g_dinv[i] = rsqrtf((float)(c + 1));
}
__global__ void k_fill(const int* __restrict__ src, const int* __restrict__ dst, int e) {
    int i = blockIdx.x * blockDim.x + threadIdx.x;
    if (i >= e) return;
    int d = dst[i];
    int p = atomicAdd(&g_cur[d], 1);
    g_es[p] = src[i];
}

// ---------------- tensor-core GEMM (m16n8k16 HMMA): Y = X @ W, fp8 out -------------
// 128 rows/block, 256 threads (8 warps x 16 rows). A,W -> fp16 smem; C -> smem fp32;
// epilogues read Cs in the legacy (tx,ty) layout (unchanged logic).
template <int K, int J, int SD, bool SCALE>
__global__ __launch_bounds__(256)
void k_gemm(const float* __restrict__ X, const float* __restrict__ W,
            unsigned char* __restrict__ Y, const float* __restrict__ asv,
            const float* __restrict__ adv, int n) {
    constexpr int SA = K + 8;           // padded half stride (bank-conflict-free)
    constexpr int JT = J / 64;
    extern __shared__ char smem[];
    __half* As = (__half*)smem;                          // [128][SA]
    __half* Wt = (__half*)(smem + 128 * SA * 2);         // [J][SA] (W transposed)
    float*  Cs = (float*)smem;                           // [128][J], aliases As/Wt

    int tid = threadIdx.x;
    int wid = tid >> 5, l = tid & 31;
    int gid = l >> 2, tig = l & 3;
    int row0 = blockIdx.x * 128;

    // load A (fp32 -> fp16), zero-pad OOB rows
    const int HK = K / 2;
    for (int idx = tid; idx < 128 * HK; idx += 256) {
        int r = idx / HK, c2 = idx % HK;
        int gr = row0 + r;
        float2 v = (gr < n) ? ((const float2*)X)[(size_t)gr * HK + c2]
                            : make_float2(0.f, 0.f);
        *(__half2*)&As[r * SA + c2 * 2] = __floats2half2_rn(v.x, v.y);
    }
    // load W transposed: Wt[j][k]
    for (int idx = tid; idx < K * J; idx += 256) {
        int k = idx / J, j = idx % J;
        Wt[j * SA + k] = __float2half_rn(W[idx]);
    }
    __syncthreads();

    // mma mainloop: warp owns rows [wid*16, +16), all J cols
    float cfr[J / 8][4];
#pragma unroll
    for (int jt = 0; jt < J / 8; jt++)
#pragma unroll
        for (int c = 0; c < 4; c++) cfr[jt][c] = 0.f;

    const __half* Ar = As + (wid * 16) * SA;
#pragma unroll
    for (int k0 = 0; k0 < K; k0 += 16) {
        unsigned a0 = *(const unsigned*)&Ar[gid * SA + k0 + tig * 2];
        unsigned a1 = *(const unsigned*)&Ar[(gid + 8) * SA + k0 + tig * 2];
        unsigned a2 = *(const unsigned*)&Ar[gid * SA + k0 + 8 + tig * 2];
        unsigned a3 = *(const unsigned*)&Ar[(gid + 8) * SA + k0 + 8 + tig * 2];
#pragma unroll
        for (int jt = 0; jt < J / 8; jt++) {
            unsigned b0 = *(const unsigned*)&Wt[(jt * 8 + gid) * SA + k0 + tig * 2];
            unsigned b1 = *(const unsigned*)&Wt[(jt * 8 + gid) * SA + k0 + 8 + tig * 2];
            mma16816(cfr[jt], a0, a1, a2, a3, b0, b1);
        }
    }
    __syncthreads();   // done reading As/Wt; Cs may now alias

    // write C fragments: thread holds (gid, tig*2..+1) and (gid+8, ...) per 8-col tile
#pragma unroll
    for (int jt = 0; jt < J / 8; jt++) {
        int r = wid * 16 + gid;
        *(float2*)&Cs[r * J + jt * 8 + tig * 2] = make_float2(cfr[jt][0], cfr[jt][1]);
        *(float2*)&Cs[(r + 8) * J + jt * 8 + tig * 2] = make_float2(cfr[jt][2], cfr[jt][3]);
    }
    __syncthreads();

    // ---- legacy epilogue layout: tx in 0..15, ty rows ty*8+i, cols jc*64+tx*4+c ----
    int tx = tid & 15, ty = tid >> 4;
    float acc[JT][8][4];
#pragma unroll
    for (int jc = 0; jc < JT; jc++)
#pragma unroll
        for (int i = 0; i < 8; i++)
            *(float4*)acc[jc][i] = *(const float4*)&Cs[(ty * 8 + i) * J + jc * 64 + tx * 4];

#pragma unroll
    for (int i = 0; i < 8; i++) {
        int gr = row0 + ty * 8 + i;
        if (gr >= n) continue;
        float dd = SCALE ? g_dinv[gr] : 1.f;
#pragma unroll
        for (int jc = 0; jc < JT; jc++) {
            unsigned st = pack_fp8x4(dd * acc[jc][i][0], dd * acc[jc][i][1],
                                     dd * acc[jc][i][2], dd * acc[jc][i][3]);
            ((unsigned*)Y)[(size_t)gr * (J / 4) + jc * 16 + tx] = st;
        }
    }

    if (SD == 1) {
        float as[2][4], ad[2][4];
#pragma unroll
        for (int jc = 0; jc < JT; jc++)
#pragma unroll
            for (int c = 0; c < 4; c++) {
                as[jc][c] = asv[jc * 64 + tx * 4 + c];
                ad[jc][c] = adv[jc * 64 + tx * 4 + c];
            }
#pragma unroll
        for (int i = 0; i < 8; i++) {
            float s0 = 0.f, d0 = 0.f, s1 = 0.f, d1 = 0.f;
#pragma unroll
            for (int c = 0; c < 4; c++) {
                s0 += acc[0][i][c] * as[0][c];
                d0 += acc[0][i][c] * ad[0][c];
                s1 += acc[JT - 1][i][c] * as[1][c];
                d1 += acc[JT - 1][i][c] * ad[1][c];
            }
#pragma unroll
            for (int o = 8; o; o >>= 1) {
                s0 += __shfl_xor_sync(FULL, s0, o);
                d0 += __shfl_xor_sync(FULL, d0, o);
                s1 += __shfl_xor_sync(FULL, s1, o);
                d1 += __shfl_xor_sync(FULL, d1, o);
            }
            int gr = row0 + ty * 8 + i;
            if (tx == 0 && gr < n) {
                g_Sv[gr] = make_float2(s0, s1);
                g_Dv[gr] = make_float2(d0, d1);
            }
        }
    } else if (SD == 2) {
        float as[4], ad[4];
        int h = tx >> 3;
#pragma unroll
        for (int c = 0; c < 4; c++) {
            as[c] = asv[h * 32 + (tx & 7) * 4 + c];
            ad[c] = adv[h * 32 + (tx & 7) * 4 + c];
        }
#pragma unroll
        for (int i = 0; i < 8; i++) {
            float s = 0.f, d = 0.f;
#pragma unroll
            for (int c = 0; c < 4; c++) {
                s += acc[0][i][c] * as[c];
                d += acc[0][i][c] * ad[c];
            }
#pragma unroll
            for (int o = 4; o; o >>= 1) {
                s += __shfl_xor_sync(FULL, s, o);
                d += __shfl_xor_sync(FULL, d, o);
            }
            int gr = row0 + ty * 8 + i;
            if ((tx & 7) == 0 && gr < n) {
                ((float*)g_Sv)[gr * 2 + h] = s;
                ((float*)g_Dv)[gr * 2 + h] = d;
            }
        }
    }
}

// ---------------- GCN: 4 lanes/node, fp8 rows, half2 accumulation ------------------
template <bool PRESCALED>
__global__ __launch_bounds__(160)
void k_gcn_node(const unsigned char* __restrict__ T, const float* __restrict__ b,
                float* __restrict__ X, int n) {
    int g = blockIdx.x * blockDim.x + threadIdx.x;
    int w = g >> 2;
    int lane = threadIdx.x & 3;
    unsigned gmask = 0xFu << ((threadIdx.x & 31) & ~3);
    if (w >= n) return;   // subgroup exits together; mask stays valid
    const uint4* T4 = (const uint4*)T;   // row = 64 fp8 = 4 uint4
    float dw = g_dinv[w];
    const __half2 ONE2 = __float2half2_rn(1.f);
    __half2 acch[8];
#pragma unroll
    for (int i = 0; i < 8; i++) acch[i] = __float2half2_rn(0.f);
    acc16h(T4, (size_t)w * 4 + lane, PRESCALED ? ONE2 : __float2half2_rn(dw), acch);
    int beg = g_off[w], end = beg + g_cnt[w];
    for (int base = beg; base < end; base += 4) {
        int j = base + lane;
        int sj = w;
        unsigned cpk = 0;
        if (j < end) {
            sj = g_es[j];
            if (!PRESCALED) {
                __half2 c2 = __float2half2_rn(g_dinv[sj]);
                cpk = *(unsigned*)&c2;
            }
        }
        int cnt = min(4, end - base);
        for (int t = 0; t < cnt; t++) {
            int s = __shfl_sync(gmask, sj, t, 4);
            __half2 c2v = ONE2;
            if (!PRESCALED) {
                unsigned cc = __shfl_sync(gmask, cpk, t, 4);
                c2v = *(__half2*)&cc;
            }
            acc16h(T4, (size_t)s * 4 + lane, c2v, acch);
        }
    }
    float acc[16];
    h2tof(acch, acc);
#pragma unroll
    for (int k = 0; k < 4; k++) {
        float4 bb = ((const float4*)b)[lane * 4 + k];
        float4 o;
        o.x = fmaxf(dw * acc[4 * k + 0] + bb.x, 0.f);
        o.y = fmaxf(dw * acc[4 * k + 1] + bb.y, 0.f);
        o.z = fmaxf(dw * acc[4 * k + 2] + bb.z, 0.f);
        o.w = fmaxf(dw * acc[4 * k + 3] + bb.w, 0.f);
        ((float4*)X)[(size_t)w * 16 + lane * 4 + k] = o;
    }
}

// ---------------- fused GAT layer: constant-shift softmax, fp8 rows ----------------
template <int CH, bool CONCAT>
__global__ void k_gat_node(const unsigned char* __restrict__ T,
                           const float* __restrict__ bias,
                           float* __restrict__ X, float* __restrict__ out, int n) {
    constexpr int SUBW = (CH == 64) ? 8 : 4;   // row = 2*CH fp8 = SUBW uint4
    int g = blockIdx.x * blockDim.x + threadIdx.x;
    int w = g / SUBW;
    int lane = threadIdx.x & (SUBW - 1);
    unsigned gmask = (SUBW == 8) ? (0xFFu << ((threadIdx.x & 31) & ~7))
                                 : (0xFu << ((threadIdx.x & 31) & ~3));
    if (w >= n) return;   // subgroup exits together
    float2 Dd = g_Dv[w];
    float2 Sw = g_Sv[w];
    float wself0 = __expf(lrelu(Sw.x + Dd.x) - SHIFT);
    float wself1 = __expf(lrelu(Sw.y + Dd.y) - SHIFT);
    int beg = g_off[w], end = beg + g_cnt[w];

    // --- pass 1: z = sum of exp(score - SHIFT); cache exp terms sequentially ---
    float z0 = (lane == 0) ? wself0 : 0.f;
    float z1 = (lane == 0) ? wself1 : 0.f;
    for (int j = beg + lane; j < end; j += SUBW) {
        float2 sv = g_Sv[g_es[j]];
        float w0 = __expf(lrelu(sv.x + Dd.x) - SHIFT);
        float w1 = __expf(lrelu(sv.y + Dd.y) - SHIFT);
        g_eb[j] = make_float2(w0, w1);
        z0 += w0;
        z1 += w1;
    }
#pragma unroll
    for (int o = SUBW / 2; o; o >>= 1) {
        z0 += __shfl_xor_sync(gmask, z0, o, SUBW);
        z1 += __shfl_xor_sync(gmask, z1, o, SUBW);
    }
    float iz0 = 1.f / z0;
    float iz1 = 1.f / z1;

    // --- pass 2: weighted feature accumulate; weights pre-packed as half2 ----------
    const uint4* T4 = (const uint4*)T;
    int hh = (lane >= SUBW / 2);
    __half2 acch[8];
#pragma unroll
    for (int i = 0; i < 8; i++) acch[i] = __float2half2_rn(0.f);
    float wself = hh ? wself1 * iz1 : wself0 * iz0;
    acc16h(T4, (size_t)w * SUBW + lane, __float2half2_rn(wself), acch);
    for (int base = beg; base < end; base += SUBW) {
        int j = base + lane;
        int sj = w;
        unsigned apk = 0;
        if (j < end) {
            sj = g_es[j];
            float2 eb = g_eb[j];
            __half2 ah = __halves2half2(__float2half_rn(eb.x * iz0),
                                        __float2half_rn(eb.y * iz1));
            apk = *(unsigned*)&ah;
        }
        int cnt = min(SUBW, end - base);
        for (int t = 0; t < cnt; t++) {
            int s = __shfl_sync(gmask, sj, t, SUBW);
            unsigned ap = __shfl_sync(gmask, apk, t, SUBW);
            __half2 a2 = *(__half2*)&ap;
            __half2 w2 = hh ? __high2half2(a2) : __low2half2(a2);
            acc16h(T4, (size_t)s * SUBW + lane, w2, acch);
        }
    }
    float acc[16];
    h2tof(acch, acc);

    if (CONCAT) {
#pragma unroll
        for (int k = 0; k < 4; k++) {
            float4 bb = ((const float4*)bias)[lane * 4 + k];
            float4 o;
            o.x = fmaxf(acc[4 * k + 0] + bb.x, 0.f);
            o.y = fmaxf(acc[4 * k + 1] + bb.y, 0.f);
            o.z = fmaxf(acc[4 * k + 2] + bb.z, 0.f);
            o.w = fmaxf(acc[4 * k + 3] + bb.w, 0.f);
            ((float4*)X)[(size_t)w * 32 + lane * 4 + k] = o;
        }
    } else {
        // SUBW=4: lanes 0,1 = head0 ch[lane*16..+15]; lanes 2,3 = head1 same ch.
        float v[16];
        int cl = lane & 1;
#pragma unroll
        for (int i = 0; i < 16; i++) {
            float oth = __shfl_sync(gmask, acc[i], (threadIdx.x & 2) ? (cl) : (cl + 2), 4);
            v[i] = 0.5f * (acc[i] + oth) + bias[cl * 16 + i];
        }
        float mx = v[0];
#pragma unroll
        for (int i = 1; i < 16; i++) mx = fmaxf(mx, v[i]);
        mx = fmaxf(mx, __shfl_xor_sync(gmask, mx, 1, 4));
        float sum = 0.f;
#pragma unroll
        for (int i = 0; i < 16; i++) sum += __expf(v[i] - mx);
        sum += __shfl_xor_sync(gmask, sum, 1, 4);
        float ls = logf(sum);
        if (lane < 2) {
#pragma unroll
            for (int k = 0; k < 4; k++) {
                float4 o;
                o.x = v[4 * k + 0] - mx - ls;
                o.y = v[4 * k + 1] - mx - ls;
                o.z = v[4 * k + 2] - mx - ls;
                o.w = v[4 * k + 3] - mx - ls;
                ((float4*)out)[(size_t)w * 8 + cl * 4 + k] = o;
            }
        }
    }
}

// ---------------- launcher ----------------
static inline int cdiv(long long a, int b) { return (int)((a + b - 1) / b); }
static inline int gemm_smem(int K, int J) {
    int ab = 128 * (K + 8) * 2 + J * (K + 8) * 2;
    int cs = 128 * J * 4;
    return ab > cs ? ab : cs;
}

extern "C" void kernel_launch(void* const* d_in, const int* in_sizes, int n_in,
                              void* d_out, int out_size) {
    const float* x   = (const float*)d_in[0];
    const int*   ei  = (const int*)d_in[1];
    const float* W1  = (const float*)d_in[2];
    const float* b1  = (const float*)d_in[3];
    const float* W2  = (const float*)d_in[4];
    const float* b2  = (const float*)d_in[5];
    const float* Wg1 = (const float*)d_in[6];
    const float* as1 = (const float*)d_in[7];
    const float* ad1 = (const float*)d_in[8];
    const float* bg1 = (const float*)d_in[9];
    const float* Wg2 = (const float*)d_in[10];
    const float* as2 = (const float*)d_in[11];
    const float* ad2 = (const float*)d_in[12];
    const float* bg2 = (const float*)d_in[13];

    int n = in_sizes[0] / 128;
    int e = in_sizes[1] / 2;
    const int* src = ei;
    const int* dst = ei + e;

    unsigned char* T = nullptr; cudaGetSymbolAddress((void**)&T, g_bufT);
    float* X = nullptr; cudaGetSymbolAddress((void**)&X, g_bufX);
    float* out = (float*)d_out;

    static cudaStream_t s1 = nullptr;
    static cudaEvent_t e0 = nullptr, eCsr = nullptr;
    if (!s1) {
        cudaStreamCreateWithFlags(&s1, cudaStreamNonBlocking);
        cudaEventCreateWithFlags(&e0, cudaEventDisableTiming);
        cudaEventCreateWithFlags(&eCsr, cudaEventDisableTiming);
        cudaFuncSetAttribute(k_gemm<128, 64, 0, false>,
                             cudaFuncAttributeMaxDynamicSharedMemorySize, gemm_smem(128, 64));
        cudaFuncSetAttribute(k_gemm<64, 64, 0, true>,
                             cudaFuncAttributeMaxDynamicSharedMemorySize, gemm_smem(64, 64));
        cudaFuncSetAttribute(k_gemm<64, 128, 1, false>,
                             cudaFuncAttributeMaxDynamicSharedMemorySize, gemm_smem(64, 128));
        cudaFuncSetAttribute(k_gemm<128, 64, 2, false>,
                             cudaFuncAttributeMaxDynamicSharedMemorySize, gemm_smem(128, 64));
    }

    const int B = 256;
    int quad_blocks = cdiv((long long)n * 4, 160);    // 1250 exact (block=160)
    int oct_blocks  = cdiv((long long)n * 8, 128);    // 3125 exact (block=128)
    int gemm_blocks = cdiv(n, 128);

    // --- fork: CSR build on side stream (fully overlapped with GEMM1) ---
    cudaEventRecord(e0, 0);
    cudaStreamWaitEvent(s1, e0, 0);
    k_cnt_zero<<<cdiv(n, B), B, 0, s1>>>(n);
    k_hist<<<cdiv(e, B), B, 0, s1>>>(dst, e);
    k_off<<<cdiv(n, B), B, 0, s1>>>(n);
    k_fill<<<cdiv(e, B), B, 0, s1>>>(src, dst, e);
    cudaEventRecord(eCsr, s1);

    // --- GCN1: 128 -> 64 (no dinv dependency; per-edge dinv in node kernel) ---
    k_gemm<128, 64, 0, false><<<gemm_blocks, 256, gemm_smem(128, 64)>>>(
        x, W1, T, nullptr, nullptr, n);
    cudaStreamWaitEvent(0, eCsr, 0);     // CSR + dinv ready before aggregation
    k_gcn_node<false><<<quad_blocks, 160>>>(T, b1, X, n);

    // --- GCN2: 64 -> 64 (rows pre-scaled by dinv; dinv already synced) ---
    k_gemm<64, 64, 0, true><<<gemm_blocks, 256, gemm_smem(64, 64)>>>(
        X, W2, T, nullptr, nullptr, n);
    k_gcn_node<true><<<quad_blocks, 160>>>(T, b2, X, n);

    // --- GAT1: 64 -> 2x64 concat (scores fused into GEMM epilogue) ---
    k_gemm<64, 128, 1, false><<<gemm_blocks, 256, gemm_smem(64, 128)>>>(
        X, Wg1, T, as1, ad1, n);
    k_gat_node<64, true><<<oct_blocks, 128>>>(T, bg1, X, nullptr, n);

    // --- GAT2: 128 -> 2x32 mean + log_softmax ---
    k_gemm<128, 64, 2, false><<<gemm_blocks, 256, gemm_smem(128, 64)>>>(
        X, Wg2, T, as2, ad2, n);
    k_gat_node<32, false><<<quad_blocks, 160>>>(T, bg2, nullptr, out, n);
}